// round 14
// baseline (speedup 1.0000x reference)
#include <cuda_runtime.h>
#include <cuda_fp16.h>
#include <cstdint>
#include <cstddef>

#define NB  256
#define SL  64
#define NH  64
#define HD  64
#define EMB 4096
#define LOG2E_O8 0.1803368801111204f
#define WSCALE    256.0f
#define INV_WSCALE 0.00390625f

// g_P: masked (n,l) tiles are NEVER written by any kernel; device globals are
// zero-initialized (.bss), so those tiles read deterministically as 0.
__device__ __half g_wh[(size_t)EMB * EMB];            // fp16(w*256) [N][K]
__device__ __half g_vsumT[NB * HD * SL];              // [n][d][l]
__device__ __half g_P[(size_t)NB * SL * NH * NH];     // fp16 exp(E/8); masked tiles stay 0
__device__ float  g_zinv[SL * NH * NH];               // [l][a][b]
__device__ __half g_X[(size_t)NB * NH * EMB];         // [16384][4096]

// ---------- helpers ----------
__device__ __forceinline__ void cp16(uint32_t dst, const void* src) {
    asm volatile("cp.async.cg.shared.global [%0], [%1], 16;" :: "r"(dst), "l"(src));
}
#define CP_COMMIT() asm volatile("cp.async.commit_group;" ::: "memory")
#define CP_WAIT(n)  asm volatile("cp.async.wait_group %0;" :: "n"(n) : "memory")

__device__ __forceinline__ void ldm_x4(uint32_t* r, const __half* p) {
    uint32_t a = (uint32_t)__cvta_generic_to_shared(p);
    asm volatile("ldmatrix.sync.aligned.m8n8.x4.shared.b16 {%0,%1,%2,%3}, [%4];"
                 : "=r"(r[0]), "=r"(r[1]), "=r"(r[2]), "=r"(r[3]) : "r"(a));
}
__device__ __forceinline__ void ldm_x4_t(uint32_t* r, const __half* p) {
    uint32_t a = (uint32_t)__cvta_generic_to_shared(p);
    asm volatile("ldmatrix.sync.aligned.m8n8.x4.trans.shared.b16 {%0,%1,%2,%3}, [%4];"
                 : "=r"(r[0]), "=r"(r[1]), "=r"(r[2]), "=r"(r[3]) : "r"(a));
}
__device__ __forceinline__ void mma16816(float* c, const uint32_t* a, uint32_t b0, uint32_t b1) {
    asm volatile(
        "mma.sync.aligned.m16n8k16.row.col.f32.f16.f16.f32 "
        "{%0,%1,%2,%3}, {%4,%5,%6,%7}, {%8,%9}, {%0,%1,%2,%3};"
        : "+f"(c[0]), "+f"(c[1]), "+f"(c[2]), "+f"(c[3])
        : "r"(a[0]), "r"(a[1]), "r"(a[2]), "r"(a[3]), "r"(b0), "r"(b1));
}
// 64x64x64 core on a 4-warp group; wtid = tid within the 128-thread group.
__device__ __forceinline__ void gemm64_core_g(int wtid, const __half* sA, const __half* sB,
                                              float acc[8][4]) {
    int w = wtid >> 5, lane = wtid & 31;
    int lr = lane & 15, lc = lane >> 4;
#pragma unroll
    for (int kt = 0; kt < 4; kt++) {
        uint32_t af[4];
        ldm_x4(af, &sA[(w * 16 + lr) * 72 + kt * 16 + lc * 8]);
#pragma unroll
        for (int bp = 0; bp < 4; bp++) {
            uint32_t bf[4];
            ldm_x4(bf, &sB[(bp * 16 + lr) * 72 + kt * 16 + lc * 8]);
            mma16816(acc[bp * 2],     af, bf[0], bf[2]);
            mma16816(acc[bp * 2 + 1], af, bf[1], bf[3]);
        }
    }
}

// ---------- K1: fused energy + weight-convert + Vsum ----------
// blocks [0,16384): energy; [16384,49152): convw; [49152,57344): vsum.
// prep blocks backfill SMs freed by masked energy blocks' early exit.
__global__ void __launch_bounds__(128) k_energy(const float* __restrict__ q,
                                                const float* __restrict__ kk,
                                                const int* __restrict__ mask,
                                                const float* __restrict__ w,
                                                const float* __restrict__ values) {
    __shared__ __half sbuf[2 * 64 * 72];       // sA | sB; sEh aliased after MMA
    int bid = blockIdx.x;
    if (bid >= 16384) {
        if (bid < 49152) {                     // convw: 4.19M float4 chunks
            size_t i = (size_t)(bid - 16384) * 128 + threadIdx.x;
            float4 v = ((const float4*)w)[i];
            __half2* o = (__half2*)g_wh;
            o[i * 2]     = __floats2half2_rn(v.x * WSCALE, v.y * WSCALE);
            o[i * 2 + 1] = __floats2half2_rn(v.z * WSCALE, v.w * WSCALE);
        } else {                               // vsum: 1M outputs
            int t = (bid - 49152) * 128 + threadIdx.x;
            int d = t & 63, l = (t >> 6) & 63, n = t >> 12;
            const float* p = values + ((size_t)(n * 64 + l)) * EMB + d;
            float s = 0.f;
#pragma unroll
            for (int v = 0; v < 64; v++) s += p[v * 64];
            g_vsumT[(n * 64 + d) * 64 + l] = __float2half_rn(s);
        }
        return;
    }
    int nl = bid;
    if (mask[nl] == 0) return;                 // tile stays 0 (never written)
    __half* sA  = sbuf;
    __half* sB  = sbuf + 64 * 72;
    __half* sEh = sbuf;
    __half* po = g_P + (size_t)nl * 4096;
    const float* qr = q  + (size_t)nl * EMB;
    const float* kr = kk + (size_t)nl * EMB;
#pragma unroll
    for (int i = threadIdx.x; i < 1024; i += 128) {   // float4 loads
        int r = i >> 4, cq = (i & 15) * 4;
        float4 v = ((const float4*)qr)[i];
        __half2* d = (__half2*)&sA[r * 72 + cq];
        d[0] = __floats2half2_rn(v.x, v.y);
        d[1] = __floats2half2_rn(v.z, v.w);
        float4 u = ((const float4*)kr)[i];
        __half2* e = (__half2*)&sB[r * 72 + cq];
        e[0] = __floats2half2_rn(u.x, u.y);
        e[1] = __floats2half2_rn(u.z, u.w);
    }
    __syncthreads();
    float acc[8][4];
#pragma unroll
    for (int i = 0; i < 8; i++) acc[i][0] = acc[i][1] = acc[i][2] = acc[i][3] = 0.f;
    gemm64_core_g(threadIdx.x, sA, sB, acc);
    __syncthreads();                           // sA/sB dead; reuse as sEh
    int lane = threadIdx.x & 31, w4 = threadIdx.x >> 5;
    int r0 = w4 * 16 + (lane >> 2), c0 = (lane & 3) * 2;
#pragma unroll
    for (int nt = 0; nt < 8; nt++) {           // conflict-free half2 stores
        int col = nt * 8 + c0;
        *(__half2*)&sEh[r0 * 72 + col] = __floats2half2_rn(
            exp2f(acc[nt][0] * LOG2E_O8), exp2f(acc[nt][1] * LOG2E_O8));
        *(__half2*)&sEh[(r0 + 8) * 72 + col] = __floats2half2_rn(
            exp2f(acc[nt][2] * LOG2E_O8), exp2f(acc[nt][3] * LOG2E_O8));
    }
    __syncthreads();
#pragma unroll
    for (int i4 = threadIdx.x; i4 < 512; i4 += 128) {   // 16B copies
        int r = i4 >> 3, c8 = (i4 & 7) * 8;
        ((int4*)po)[i4] = *(int4*)&sEh[r * 72 + c8];
    }
}

// ---------- K2: zinv = 1 / sum_n P (masked tiles are 0 => contribute 0) -----
__global__ void __launch_bounds__(256) k_zsum() {
    int c2 = blockIdx.x * 256 + threadIdx.x;      // 131072 half2 columns
    const __half2* p = (const __half2*)g_P + c2;
    float zx = 0.f, zy = 0.f;
#pragma unroll 16
    for (int n = 0; n < NB; n++) {
        float2 v = __half22float2(p[(size_t)n * 131072]);
        zx += v.x; zy += v.y;
    }
    int c = c2 * 2;
    g_zinv[c]     = (zx > 0.f) ? (1.f / zx) : 0.f;
    g_zinv[c + 1] = (zy > 0.f) ? (1.f / zy) : 0.f;
}

// ---------- K3: X[b*256+n][qh*64+d], 2 query-heads per 256-thread block -----
// Warp-group g (128 thr) handles qh = qp*2+g; both groups share one sV tile.
__global__ void __launch_bounds__(256) k_attv() {
    __shared__ __half sbuf[3 * 64 * 72];
    __half* sV = sbuf + 2 * 64 * 72;    // [d][l], shared by both groups
    int n  = blockIdx.x >> 5;
    int qp = blockIdx.x & 31;
    int g    = threadIdx.x >> 7;        // warp-group 0/1
    int wtid = threadIdx.x & 127;
    int qh   = qp * 2 + g;
    __half* sP  = sbuf + g * 64 * 72;   // [l][b] scaled att (per group)
    __half* sOh = sP;                   // aliased after MMA

    for (int i4 = threadIdx.x; i4 < 512; i4 += 256) {   // sV fill, 16B, all threads
        int d = i4 >> 3, lc = (i4 & 7) * 8;
        *(int4*)&sV[d * 72 + lc] = *(const int4*)&g_vsumT[n * 4096 + d * 64 + lc];
    }
#pragma unroll
    for (int i4 = wtid; i4 < 512; i4 += 128) {
        int l = i4 >> 3, b = (i4 & 7) * 8;
        int4 pr = *(const int4*)&g_P[((size_t)(n * 64 + l)) * 4096 + qh * 64 + b];
        __half2* ph = (__half2*)&pr;
        const float* zp = &g_zinv[(l * 64 + qh) * 64 + b];
        float4 z0 = *(const float4*)zp;
        float4 z1 = *(const float4*)(zp + 4);
        __half2 h[4];
        {
            float2 p0 = __half22float2(ph[0]);
            float2 p1 = __half22float2(ph[1]);
            float2 p2 = __half22float2(ph[2]);
            float2 p3 = __half22float2(ph[3]);
            h[0] = __floats2half2_rn(p0.x * z0.x, p0.y * z0.y);
            h[1] = __floats2half2_rn(p1.x * z0.z, p1.y * z0.w);
            h[2] = __floats2half2_rn(p2.x * z1.x, p2.y * z1.y);
            h[3] = __floats2half2_rn(p3.x * z1.z, p3.y * z1.w);
        }
        *(int4*)&sP[l * 72 + b] = *(int4*)h;   // conflict-free 16B store
    }
    __syncthreads();
    float acc[8][4];
#pragma unroll
    for (int i = 0; i < 8; i++) acc[i][0] = acc[i][1] = acc[i][2] = acc[i][3] = 0.f;
    {
        int w = wtid >> 5, lane = wtid & 31;
        int lr = lane & 15, lc = lane >> 4;
        int tr = (lane & 7) + ((lane >> 4) << 3);
        int tc = ((lane >> 3) & 1) << 3;
#pragma unroll
        for (int kt = 0; kt < 4; kt++) {
            uint32_t af[4];
            ldm_x4_t(af, &sP[(kt * 16 + tr) * 72 + w * 16 + tc]);
#pragma unroll
            for (int bp = 0; bp < 4; bp++) {
                uint32_t bf[4];
                ldm_x4(bf, &sV[(bp * 16 + lr) * 72 + kt * 16 + lc * 8]);
                mma16816(acc[bp * 2],     af, bf[0], bf[2]);
                mma16816(acc[bp * 2 + 1], af, bf[1], bf[3]);
            }
        }
    }
    __syncthreads();                   // sP dead in both groups; reuse as sOh
    int lane = wtid & 31, w4 = wtid >> 5;
    int r0 = w4 * 16 + (lane >> 2), c0 = (lane & 3) * 2;
#pragma unroll
    for (int nt = 0; nt < 8; nt++) {   // conflict-free half2 stores
        int col = nt * 8 + c0;
        *(__half2*)&sOh[r0 * 72 + col] = __floats2half2_rn(acc[nt][0], acc[nt][1]);
        *(__half2*)&sOh[(r0 + 8) * 72 + col] = __floats2half2_rn(acc[nt][2], acc[nt][3]);
    }
    __syncthreads();
#pragma unroll
    for (int i4 = wtid; i4 < 512; i4 += 128) {   // 16B X copies
        int b = i4 >> 3, d = (i4 & 7) * 8;
        *(int4*)&g_X[((size_t)(b * 256 + n)) * EMB + qh * 64 + d] = *(int4*)&sOh[b * 72 + d];
    }
}

// ---------- K4: out = X @ W^T / 256 + bias (measured-best config, unchanged) --
#define BM 128
#define BN 128
#define BK 64
#define SST 72
#define A_STG (BM * SST)
#define B_STG (BN * SST)
#define GSMEM (2 * (A_STG + B_STG) * 2)      // 73728 B

__global__ void __launch_bounds__(256, 2) k_gemm(const float* __restrict__ bias,
                                                 float* __restrict__ out) {
    extern __shared__ __half smem[];
    __half* sA = smem;
    __half* sB = smem + 2 * A_STG;

    int tid = threadIdx.x;
    int pn = blockIdx.x, pm = blockIdx.y;    // pn inner => W L2-resident
    const __half* gA = g_X  + (size_t)(pm * BM) * EMB;
    const __half* gB = g_wh + (size_t)(pn * BN) * EMB;

    auto load_stage = [&](int kt, int s) {
#pragma unroll
        for (int i = 0; i < 4; i++) {
            int ch = tid + i * 256;
            int row = ch >> 3, c8 = ch & 7;
            uint32_t d = (uint32_t)__cvta_generic_to_shared(&sA[s * A_STG + row * SST + c8 * 8]);
            cp16(d, gA + (size_t)row * EMB + kt * BK + c8 * 8);
        }
#pragma unroll
        for (int i = 0; i < 4; i++) {
            int ch = tid + i * 256;
            int row = ch >> 3, c8 = ch & 7;
            uint32_t d = (uint32_t)__cvta_generic_to_shared(&sB[s * B_STG + row * SST + c8 * 8]);
            cp16(d, gB + (size_t)row * EMB + kt * BK + c8 * 8);
        }
    };

    int w = tid >> 5, lane = tid & 31;
    int wm = (w & 1) * 64, wn = (w >> 1) * 32;
    int lr = lane & 15, lc = lane >> 4;

    float acc[4][4][4];
#pragma unroll
    for (int m = 0; m < 4; m++)
#pragma unroll
        for (int nn = 0; nn < 4; nn++)
#pragma unroll
            for (int x = 0; x < 4; x++) acc[m][nn][x] = 0.f;

    const int KT = EMB / BK;   // 64
    load_stage(0, 0); CP_COMMIT();

    for (int kt = 0; kt < KT; kt++) {
        CP_WAIT(0);
        __syncthreads();
        if (kt + 1 < KT) { load_stage(kt + 1, (kt + 1) & 1); CP_COMMIT(); }
        const __half* cA = sA + (kt & 1) * A_STG;
        const __half* cB = sB + (kt & 1) * B_STG;
#pragma unroll
        for (int ks = 0; ks < 4; ks++) {
            uint32_t af[4][4];
#pragma unroll
            for (int mt = 0; mt < 4; mt++)
                ldm_x4(af[mt], &cA[(wm + mt * 16 + lr) * SST + ks * 16 + lc * 8]);
#pragma unroll
            for (int ng = 0; ng < 2; ng++) {
                uint32_t bf[4];
                ldm_x4(bf, &cB[(wn + ng * 16 + lr) * SST + ks * 16 + lc * 8]);
#pragma unroll
                for (int mt = 0; mt < 4; mt++) {
                    mma16816(acc[mt][ng * 2],     af[mt], bf[0], bf[2]);
                    mma16816(acc[mt][ng * 2 + 1], af[mt], bf[1], bf[3]);
                }
            }
        }
    }

    int r = lane >> 2, c = (lane & 3) * 2;
#pragma unroll
    for (int mt = 0; mt < 4; mt++) {
        int row0 = pm * BM + wm + mt * 16 + r;
#pragma unroll
        for (int nt = 0; nt < 4; nt++) {
            int col = pn * BN + wn + nt * 8 + c;
            float b0 = bias[col], b1 = bias[col + 1];
            size_t o0 = (size_t)row0 * EMB + col;
            out[o0]     = acc[mt][nt][0] * INV_WSCALE + b0;
            out[o0 + 1] = acc[mt][nt][1] * INV_WSCALE + b1;
            size_t o1 = (size_t)(row0 + 8) * EMB + col;
            out[o1]     = acc[mt][nt][2] * INV_WSCALE + b0;
            out[o1 + 1] = acc[mt][nt][3] * INV_WSCALE + b1;
        }
    }
}

// ---------- launch ----------
extern "C" void kernel_launch(void* const* d_in, const int* in_sizes, int n_in,
                              void* d_out, int out_size) {
    const float* values = (const float*)d_in[0];
    const float* keys   = (const float*)d_in[1];
    const float* query  = (const float*)d_in[2];
    const int*   mask   = (const int*)d_in[3];
    const float* w_out  = (const float*)d_in[4];
    const float* b_out  = (const float*)d_in[5];
    float* out = (float*)d_out;

    cudaFuncSetAttribute(k_gemm, cudaFuncAttributeMaxDynamicSharedMemorySize, GSMEM);

    k_energy<<<57344, 128>>>(query, keys, mask, w_out, values);  // fused + prep
    k_zsum<<<512, 256>>>();
    k_attv<<<NB * NH / 2, 256>>>();
    dim3 g5(EMB / BN, (NB * NH) / BM);   // (32, 128), pn inner
    k_gemm<<<g5, 256, GSMEM>>>(b_out, out);
}

// round 15
// speedup vs baseline: 1.4915x; 1.4915x over previous
#include <cuda_runtime.h>
#include <cuda_fp16.h>
#include <cstdint>
#include <cstddef>

#define NB  256
#define SL  64
#define NH  64
#define HD  64
#define EMB 4096
#define LOG2E_O8 0.1803368801111204f
#define WSCALE    256.0f
#define INV_WSCALE 0.00390625f

// g_P: masked (n,l) tiles are NEVER written by any kernel; device globals are
// zero-initialized (.bss), so those tiles read deterministically as 0.
__device__ __half g_wh[(size_t)EMB * EMB];            // fp16(w*256) [N][K]
__device__ __half g_vsumT[NB * HD * SL];              // [n][d][l]
__device__ __half g_P[(size_t)NB * SL * NH * NH];     // fp16 exp(E/8); masked tiles stay 0
__device__ float  g_zinv[SL * NH * NH];               // [l][a][b]
__device__ __half g_X[(size_t)NB * NH * EMB];         // [16384][4096]

// ---------- helpers ----------
__device__ __forceinline__ void cp16(uint32_t dst, const void* src) {
    asm volatile("cp.async.cg.shared.global [%0], [%1], 16;" :: "r"(dst), "l"(src));
}
#define CP_COMMIT() asm volatile("cp.async.commit_group;" ::: "memory")
#define CP_WAIT(n)  asm volatile("cp.async.wait_group %0;" :: "n"(n) : "memory")

__device__ __forceinline__ void ldm_x4(uint32_t* r, const __half* p) {
    uint32_t a = (uint32_t)__cvta_generic_to_shared(p);
    asm volatile("ldmatrix.sync.aligned.m8n8.x4.shared.b16 {%0,%1,%2,%3}, [%4];"
                 : "=r"(r[0]), "=r"(r[1]), "=r"(r[2]), "=r"(r[3]) : "r"(a));
}
__device__ __forceinline__ void ldm_x4_t(uint32_t* r, const __half* p) {
    uint32_t a = (uint32_t)__cvta_generic_to_shared(p);
    asm volatile("ldmatrix.sync.aligned.m8n8.x4.trans.shared.b16 {%0,%1,%2,%3}, [%4];"
                 : "=r"(r[0]), "=r"(r[1]), "=r"(r[2]), "=r"(r[3]) : "r"(a));
}
__device__ __forceinline__ void mma16816(float* c, const uint32_t* a, uint32_t b0, uint32_t b1) {
    asm volatile(
        "mma.sync.aligned.m16n8k16.row.col.f32.f16.f16.f32 "
        "{%0,%1,%2,%3}, {%4,%5,%6,%7}, {%8,%9}, {%0,%1,%2,%3};"
        : "+f"(c[0]), "+f"(c[1]), "+f"(c[2]), "+f"(c[3])
        : "r"(a[0]), "r"(a[1]), "r"(a[2]), "r"(a[3]), "r"(b0), "r"(b1));
}
__device__ __forceinline__ void gemm64_core(const __half* sA, const __half* sB, float acc[8][4]) {
    int w = threadIdx.x >> 5, lane = threadIdx.x & 31;
    int lr = lane & 15, lc = lane >> 4;
#pragma unroll
    for (int kt = 0; kt < 4; kt++) {
        uint32_t af[4];
        ldm_x4(af, &sA[(w * 16 + lr) * 72 + kt * 16 + lc * 8]);
#pragma unroll
        for (int bp = 0; bp < 4; bp++) {
            uint32_t bf[4];
            ldm_x4(bf, &sB[(bp * 16 + lr) * 72 + kt * 16 + lc * 8]);
            mma16816(acc[bp * 2],     af, bf[0], bf[2]);
            mma16816(acc[bp * 2 + 1], af, bf[1], bf[3]);
        }
    }
}

// ---------- K0: merged weight-convert (16B stores) + Vsum ----------
__global__ void __launch_bounds__(1024) k_prep(const float* __restrict__ w,
                                               const float* __restrict__ values) {
    int b = blockIdx.x;
    if (b < 2048) {                       // convw: 2.1M threads x 2 float4 -> 1 int4
        size_t i2 = (size_t)b * 1024 + threadIdx.x;
        const float4* w4 = (const float4*)w;
        float4 a = w4[i2 * 2];
        float4 c = w4[i2 * 2 + 1];
        __half2 h[4];
        h[0] = __floats2half2_rn(a.x * WSCALE, a.y * WSCALE);
        h[1] = __floats2half2_rn(a.z * WSCALE, a.w * WSCALE);
        h[2] = __floats2half2_rn(c.x * WSCALE, c.y * WSCALE);
        h[3] = __floats2half2_rn(c.z * WSCALE, c.w * WSCALE);
        ((int4*)g_wh)[i2] = *(int4*)h;
    } else {                              // vsum
        int t = (b - 2048) * 1024 + threadIdx.x;
        int d = t & 63, l = (t >> 6) & 63, n = t >> 12;
        const float* p = values + ((size_t)(n * 64 + l)) * EMB + d;
        float s = 0.f;
#pragma unroll
        for (int v = 0; v < 64; v++) s += p[v * 64];
        g_vsumT[(n * 64 + d) * 64 + l] = __float2half_rn(s);
    }
}

// ---------- K1: P[n][l][a][b] = exp(E/8), unmasked tiles only ----------
// fp16 staging of exp(acc) directly from registers.
__global__ void __launch_bounds__(128) k_energy(const float* __restrict__ q,
                                                const float* __restrict__ kk,
                                                const int* __restrict__ mask) {
    __shared__ __half sbuf[2 * 64 * 72];       // sA | sB; sEh aliased after MMA
    __half* sA  = sbuf;
    __half* sB  = sbuf + 64 * 72;
    __half* sEh = sbuf;                        // 64*72 halves
    int nl = blockIdx.x;
    if (mask[nl] == 0) return;                 // tile stays 0 (never written)
    __half* po = g_P + (size_t)nl * 4096;
    const float* qr = q  + (size_t)nl * EMB;
    const float* kr = kk + (size_t)nl * EMB;
#pragma unroll
    for (int i = threadIdx.x; i < 1024; i += 128) {   // float4 loads
        int r = i >> 4, cq = (i & 15) * 4;
        float4 v = ((const float4*)qr)[i];
        __half2* d = (__half2*)&sA[r * 72 + cq];
        d[0] = __floats2half2_rn(v.x, v.y);
        d[1] = __floats2half2_rn(v.z, v.w);
        float4 u = ((const float4*)kr)[i];
        __half2* e = (__half2*)&sB[r * 72 + cq];
        e[0] = __floats2half2_rn(u.x, u.y);
        e[1] = __floats2half2_rn(u.z, u.w);
    }
    __syncthreads();
    float acc[8][4];
#pragma unroll
    for (int i = 0; i < 8; i++) acc[i][0] = acc[i][1] = acc[i][2] = acc[i][3] = 0.f;
    gemm64_core(sA, sB, acc);
    __syncthreads();                           // sA/sB dead; reuse as sEh
    int lane = threadIdx.x & 31, w = threadIdx.x >> 5;
    int r0 = w * 16 + (lane >> 2), c0 = (lane & 3) * 2;
#pragma unroll
    for (int nt = 0; nt < 8; nt++) {           // conflict-free half2 stores
        int col = nt * 8 + c0;
        *(__half2*)&sEh[r0 * 72 + col] = __floats2half2_rn(
            exp2f(acc[nt][0] * LOG2E_O8), exp2f(acc[nt][1] * LOG2E_O8));
        *(__half2*)&sEh[(r0 + 8) * 72 + col] = __floats2half2_rn(
            exp2f(acc[nt][2] * LOG2E_O8), exp2f(acc[nt][3] * LOG2E_O8));
    }
    __syncthreads();
#pragma unroll
    for (int i4 = threadIdx.x; i4 < 512; i4 += 128) {   // 16B copies
        int r = i4 >> 3, c8 = (i4 & 7) * 8;
        ((int4*)po)[i4] = *(int4*)&sEh[r * 72 + c8];
    }
}

// ---------- K2: zinv = 1 / sum_n P (int4 loads; same per-column add order) --
__global__ void __launch_bounds__(256) k_zsum() {
    int c4 = blockIdx.x * 256 + threadIdx.x;      // 32768 int4 columns/plane
    const int4* p = (const int4*)g_P + c4;
    float z[8];
#pragma unroll
    for (int j = 0; j < 8; j++) z[j] = 0.f;
#pragma unroll 8
    for (int n = 0; n < NB; n++) {
        int4 v = p[(size_t)n * 32768];
        __half2* h = (__half2*)&v;
#pragma unroll
        for (int j = 0; j < 4; j++) {
            float2 f = __half22float2(h[j]);
            z[j * 2]     += f.x;
            z[j * 2 + 1] += f.y;
        }
    }
    float* zo = g_zinv + c4 * 8;
    float4 o0, o1;
    o0.x = (z[0] > 0.f) ? (1.f / z[0]) : 0.f;
    o0.y = (z[1] > 0.f) ? (1.f / z[1]) : 0.f;
    o0.z = (z[2] > 0.f) ? (1.f / z[2]) : 0.f;
    o0.w = (z[3] > 0.f) ? (1.f / z[3]) : 0.f;
    o1.x = (z[4] > 0.f) ? (1.f / z[4]) : 0.f;
    o1.y = (z[5] > 0.f) ? (1.f / z[5]) : 0.f;
    o1.z = (z[6] > 0.f) ? (1.f / z[6]) : 0.f;
    o1.w = (z[7] > 0.f) ? (1.f / z[7]) : 0.f;
    *(float4*)zo = o0;
    *(float4*)(zo + 4) = o1;
}

// ---------- K3: X[b*256+n][qh*64+d] ----------
// att in natural [l][b] layout; A via ldmatrix.trans; fp16 epilogue staging.
__global__ void __launch_bounds__(128) k_attv() {
    __shared__ __half sbuf[2 * 64 * 72];
    __half* sP  = sbuf;                 // [l][b] scaled att
    __half* sV  = sbuf + 64 * 72;       // [d][l]
    __half* sOh = sbuf;                 // aliased after MMA, [b][d] stride 72
    int n  = blockIdx.x >> 6;
    int qh = blockIdx.x & 63;
#pragma unroll
    for (int i4 = threadIdx.x; i4 < 512; i4 += 128) {   // sV fill, 16B
        int d = i4 >> 3, lc = (i4 & 7) * 8;
        *(int4*)&sV[d * 72 + lc] = *(const int4*)&g_vsumT[n * 4096 + d * 64 + lc];
    }
#pragma unroll
    for (int i4 = threadIdx.x; i4 < 512; i4 += 128) {
        int l = i4 >> 3, b = (i4 & 7) * 8;
        int4 pr = *(const int4*)&g_P[((size_t)(n * 64 + l)) * 4096 + qh * 64 + b];
        __half2* ph = (__half2*)&pr;
        const float* zp = &g_zinv[(l * 64 + qh) * 64 + b];
        float4 z0 = *(const float4*)zp;
        float4 z1 = *(const float4*)(zp + 4);
        __half2 h[4];
        {
            float2 p0 = __half22float2(ph[0]);
            float2 p1 = __half22float2(ph[1]);
            float2 p2 = __half22float2(ph[2]);
            float2 p3 = __half22float2(ph[3]);
            h[0] = __floats2half2_rn(p0.x * z0.x, p0.y * z0.y);
            h[1] = __floats2half2_rn(p1.x * z0.z, p1.y * z0.w);
            h[2] = __floats2half2_rn(p2.x * z1.x, p2.y * z1.y);
            h[3] = __floats2half2_rn(p3.x * z1.z, p3.y * z1.w);
        }
        *(int4*)&sP[l * 72 + b] = *(int4*)h;   // conflict-free 16B store
    }
    __syncthreads();
    float acc[8][4];
#pragma unroll
    for (int i = 0; i < 8; i++) acc[i][0] = acc[i][1] = acc[i][2] = acc[i][3] = 0.f;
    {
        int w = threadIdx.x >> 5, lane = threadIdx.x & 31;
        int lr = lane & 15, lc = lane >> 4;
        int tr = (lane & 7) + ((lane >> 4) << 3);
        int tc = ((lane >> 3) & 1) << 3;
#pragma unroll
        for (int kt = 0; kt < 4; kt++) {
            uint32_t af[4];
            ldm_x4_t(af, &sP[(kt * 16 + tr) * 72 + w * 16 + tc]);
#pragma unroll
            for (int bp = 0; bp < 4; bp++) {
                uint32_t bf[4];
                ldm_x4(bf, &sV[(bp * 16 + lr) * 72 + kt * 16 + lc * 8]);
                mma16816(acc[bp * 2],     af, bf[0], bf[2]);
                mma16816(acc[bp * 2 + 1], af, bf[1], bf[3]);
            }
        }
    }
    __syncthreads();                   // sP/sV dead; reuse as sOh
    int lane = threadIdx.x & 31, w = threadIdx.x >> 5;
    int r0 = w * 16 + (lane >> 2), c0 = (lane & 3) * 2;
#pragma unroll
    for (int nt = 0; nt < 8; nt++) {   // conflict-free half2 stores
        int col = nt * 8 + c0;
        *(__half2*)&sOh[r0 * 72 + col] = __floats2half2_rn(acc[nt][0], acc[nt][1]);
        *(__half2*)&sOh[(r0 + 8) * 72 + col] = __floats2half2_rn(acc[nt][2], acc[nt][3]);
    }
    __syncthreads();
#pragma unroll
    for (int i4 = threadIdx.x; i4 < 512; i4 += 128) {   // 16B X copies
        int b = i4 >> 3, d = (i4 & 7) * 8;
        *(int4*)&g_X[((size_t)(b * 256 + n)) * EMB + qh * 64 + d] = *(int4*)&sOh[b * 72 + d];
    }
}

// ---------- K4: out = X @ W^T / 256 + bias (measured-best config, unchanged) --
#define BM 128
#define BN 128
#define BK 64
#define SST 72
#define A_STG (BM * SST)
#define B_STG (BN * SST)
#define GSMEM (2 * (A_STG + B_STG) * 2)      // 73728 B

__global__ void __launch_bounds__(256, 2) k_gemm(const float* __restrict__ bias,
                                                 float* __restrict__ out) {
    extern __shared__ __half smem[];
    __half* sA = smem;
    __half* sB = smem + 2 * A_STG;

    int tid = threadIdx.x;
    int pn = blockIdx.x, pm = blockIdx.y;    // pn inner => W L2-resident
    const __half* gA = g_X  + (size_t)(pm * BM) * EMB;
    const __half* gB = g_wh + (size_t)(pn * BN) * EMB;

    auto load_stage = [&](int kt, int s) {
#pragma unroll
        for (int i = 0; i < 4; i++) {
            int ch = tid + i * 256;
            int row = ch >> 3, c8 = ch & 7;
            uint32_t d = (uint32_t)__cvta_generic_to_shared(&sA[s * A_STG + row * SST + c8 * 8]);
            cp16(d, gA + (size_t)row * EMB + kt * BK + c8 * 8);
        }
#pragma unroll
        for (int i = 0; i < 4; i++) {
            int ch = tid + i * 256;
            int row = ch >> 3, c8 = ch & 7;
            uint32_t d = (uint32_t)__cvta_generic_to_shared(&sB[s * B_STG + row * SST + c8 * 8]);
            cp16(d, gB + (size_t)row * EMB + kt * BK + c8 * 8);
        }
    };

    int w = tid >> 5, lane = tid & 31;
    int wm = (w & 1) * 64, wn = (w >> 1) * 32;
    int lr = lane & 15, lc = lane >> 4;

    float acc[4][4][4];
#pragma unroll
    for (int m = 0; m < 4; m++)
#pragma unroll
        for (int nn = 0; nn < 4; nn++)
#pragma unroll
            for (int x = 0; x < 4; x++) acc[m][nn][x] = 0.f;

    const int KT = EMB / BK;   // 64
    load_stage(0, 0); CP_COMMIT();

    for (int kt = 0; kt < KT; kt++) {
        CP_WAIT(0);
        __syncthreads();
        if (kt + 1 < KT) { load_stage(kt + 1, (kt + 1) & 1); CP_COMMIT(); }
        const __half* cA = sA + (kt & 1) * A_STG;
        const __half* cB = sB + (kt & 1) * B_STG;
#pragma unroll
        for (int ks = 0; ks < 4; ks++) {
            uint32_t af[4][4];
#pragma unroll
            for (int mt = 0; mt < 4; mt++)
                ldm_x4(af[mt], &cA[(wm + mt * 16 + lr) * SST + ks * 16 + lc * 8]);
#pragma unroll
            for (int ng = 0; ng < 2; ng++) {
                uint32_t bf[4];
                ldm_x4(bf, &cB[(wn + ng * 16 + lr) * SST + ks * 16 + lc * 8]);
#pragma unroll
                for (int mt = 0; mt < 4; mt++) {
                    mma16816(acc[mt][ng * 2],     af[mt], bf[0], bf[2]);
                    mma16816(acc[mt][ng * 2 + 1], af[mt], bf[1], bf[3]);
                }
            }
        }
    }

    int r = lane >> 2, c = (lane & 3) * 2;
#pragma unroll
    for (int mt = 0; mt < 4; mt++) {
        int row0 = pm * BM + wm + mt * 16 + r;
#pragma unroll
        for (int nt = 0; nt < 4; nt++) {
            int col = pn * BN + wn + nt * 8 + c;
            float b0 = bias[col], b1 = bias[col + 1];
            size_t o0 = (size_t)row0 * EMB + col;
            out[o0]     = acc[mt][nt][0] * INV_WSCALE + b0;
            out[o0 + 1] = acc[mt][nt][1] * INV_WSCALE + b1;
            size_t o1 = (size_t)(row0 + 8) * EMB + col;
            out[o1]     = acc[mt][nt][2] * INV_WSCALE + b0;
            out[o1 + 1] = acc[mt][nt][3] * INV_WSCALE + b1;
        }
    }
}

// ---------- launch ----------
extern "C" void kernel_launch(void* const* d_in, const int* in_sizes, int n_in,
                              void* d_out, int out_size) {
    const float* values = (const float*)d_in[0];
    const float* keys   = (const float*)d_in[1];
    const float* query  = (const float*)d_in[2];
    const int*   mask   = (const int*)d_in[3];
    const float* w_out  = (const float*)d_in[4];
    const float* b_out  = (const float*)d_in[5];
    float* out = (float*)d_out;

    cudaFuncSetAttribute(k_gemm, cudaFuncAttributeMaxDynamicSharedMemorySize, GSMEM);

    k_prep<<<3072, 1024>>>(w_out, values);
    k_energy<<<NB * SL, 128>>>(query, keys, mask);
    k_zsum<<<128, 256>>>();
    k_attv<<<NB * NH, 128>>>();
    dim3 g5(EMB / BN, (NB * NH) / BM);   // (32, 128), pn inner
    k_gemm<<<g5, 256, GSMEM>>>(b_out, out);
}

// round 16
// speedup vs baseline: 1.5059x; 1.0097x over previous
#include <cuda_runtime.h>
#include <cuda_fp16.h>
#include <cstdint>
#include <cstddef>

#define NB  256
#define SL  64
#define NH  64
#define HD  64
#define EMB 4096
#define LOG2E_O8 0.1803368801111204f
#define WSCALE    256.0f
#define INV_WSCALE 0.00390625f

// g_P: masked (n,l) tiles are NEVER written by any kernel; device globals are
// zero-initialized (.bss), so those tiles read deterministically as 0.
__device__ __half g_wh[(size_t)EMB * EMB];            // fp16(w*256) [N][K]
__device__ __half g_vsumT[NB * HD * SL];              // [n][d][l]
__device__ __half g_P[(size_t)NB * SL * NH * NH];     // fp16 exp(E/8); masked tiles stay 0
__device__ float  g_zinv[SL * NH * NH];               // [l][a][b]
__device__ __half g_X[(size_t)NB * NH * EMB];         // [16384][4096]

// ---------- helpers ----------
__device__ __forceinline__ void cp16(uint32_t dst, const void* src) {
    asm volatile("cp.async.cg.shared.global [%0], [%1], 16;" :: "r"(dst), "l"(src));
}
#define CP_COMMIT() asm volatile("cp.async.commit_group;" ::: "memory")
#define CP_WAIT(n)  asm volatile("cp.async.wait_group %0;" :: "n"(n) : "memory")

__device__ __forceinline__ void ldm_x4(uint32_t* r, const __half* p) {
    uint32_t a = (uint32_t)__cvta_generic_to_shared(p);
    asm volatile("ldmatrix.sync.aligned.m8n8.x4.shared.b16 {%0,%1,%2,%3}, [%4];"
                 : "=r"(r[0]), "=r"(r[1]), "=r"(r[2]), "=r"(r[3]) : "r"(a));
}
__device__ __forceinline__ void ldm_x4_t(uint32_t* r, const __half* p) {
    uint32_t a = (uint32_t)__cvta_generic_to_shared(p);
    asm volatile("ldmatrix.sync.aligned.m8n8.x4.trans.shared.b16 {%0,%1,%2,%3}, [%4];"
                 : "=r"(r[0]), "=r"(r[1]), "=r"(r[2]), "=r"(r[3]) : "r"(a));
}
__device__ __forceinline__ void mma16816(float* c, const uint32_t* a, uint32_t b0, uint32_t b1) {
    asm volatile(
        "mma.sync.aligned.m16n8k16.row.col.f32.f16.f16.f32 "
        "{%0,%1,%2,%3}, {%4,%5,%6,%7}, {%8,%9}, {%0,%1,%2,%3};"
        : "+f"(c[0]), "+f"(c[1]), "+f"(c[2]), "+f"(c[3])
        : "r"(a[0]), "r"(a[1]), "r"(a[2]), "r"(a[3]), "r"(b0), "r"(b1));
}
__device__ __forceinline__ void gemm64_core(const __half* sA, const __half* sB, float acc[8][4]) {
    int w = threadIdx.x >> 5, lane = threadIdx.x & 31;
    int lr = lane & 15, lc = lane >> 4;
#pragma unroll
    for (int kt = 0; kt < 4; kt++) {
        uint32_t af[4];
        ldm_x4(af, &sA[(w * 16 + lr) * 72 + kt * 16 + lc * 8]);
#pragma unroll
        for (int bp = 0; bp < 4; bp++) {
            uint32_t bf[4];
            ldm_x4(bf, &sB[(bp * 16 + lr) * 72 + kt * 16 + lc * 8]);
            mma16816(acc[bp * 2],     af, bf[0], bf[2]);
            mma16816(acc[bp * 2 + 1], af, bf[1], bf[3]);
        }
    }
}

// ---------- K0: merged weight-convert (16B stores) + Vsum ----------
__global__ void __launch_bounds__(1024) k_prep(const float* __restrict__ w,
                                               const float* __restrict__ values) {
    int b = blockIdx.x;
    if (b < 2048) {                       // convw: 2.1M threads x 2 float4 -> 1 int4
        size_t i2 = (size_t)b * 1024 + threadIdx.x;
        const float4* w4 = (const float4*)w;
        float4 a = w4[i2 * 2];
        float4 c = w4[i2 * 2 + 1];
        __half2 h[4];
        h[0] = __floats2half2_rn(a.x * WSCALE, a.y * WSCALE);
        h[1] = __floats2half2_rn(a.z * WSCALE, a.w * WSCALE);
        h[2] = __floats2half2_rn(c.x * WSCALE, c.y * WSCALE);
        h[3] = __floats2half2_rn(c.z * WSCALE, c.w * WSCALE);
        ((int4*)g_wh)[i2] = *(int4*)h;
    } else {                              // vsum
        int t = (b - 2048) * 1024 + threadIdx.x;
        int d = t & 63, l = (t >> 6) & 63, n = t >> 12;
        const float* p = values + ((size_t)(n * 64 + l)) * EMB + d;
        float s = 0.f;
#pragma unroll
        for (int v = 0; v < 64; v++) s += p[v * 64];
        g_vsumT[(n * 64 + d) * 64 + l] = __float2half_rn(s);
    }
}

// ---------- K1: P[n][l][a][b] = exp(E/8), unmasked tiles only ----------
// fp16 staging of exp(acc) directly from registers.
__global__ void __launch_bounds__(128) k_energy(const float* __restrict__ q,
                                                const float* __restrict__ kk,
                                                const int* __restrict__ mask) {
    __shared__ __half sbuf[2 * 64 * 72];       // sA | sB; sEh aliased after MMA
    __half* sA  = sbuf;
    __half* sB  = sbuf + 64 * 72;
    __half* sEh = sbuf;                        // 64*72 halves
    int nl = blockIdx.x;
    if (mask[nl] == 0) return;                 // tile stays 0 (never written)
    __half* po = g_P + (size_t)nl * 4096;
    const float* qr = q  + (size_t)nl * EMB;
    const float* kr = kk + (size_t)nl * EMB;
#pragma unroll
    for (int i = threadIdx.x; i < 1024; i += 128) {   // float4 loads
        int r = i >> 4, cq = (i & 15) * 4;
        float4 v = ((const float4*)qr)[i];
        __half2* d = (__half2*)&sA[r * 72 + cq];
        d[0] = __floats2half2_rn(v.x, v.y);
        d[1] = __floats2half2_rn(v.z, v.w);
        float4 u = ((const float4*)kr)[i];
        __half2* e = (__half2*)&sB[r * 72 + cq];
        e[0] = __floats2half2_rn(u.x, u.y);
        e[1] = __floats2half2_rn(u.z, u.w);
    }
    __syncthreads();
    float acc[8][4];
#pragma unroll
    for (int i = 0; i < 8; i++) acc[i][0] = acc[i][1] = acc[i][2] = acc[i][3] = 0.f;
    gemm64_core(sA, sB, acc);
    __syncthreads();                           // sA/sB dead; reuse as sEh
    int lane = threadIdx.x & 31, w = threadIdx.x >> 5;
    int r0 = w * 16 + (lane >> 2), c0 = (lane & 3) * 2;
#pragma unroll
    for (int nt = 0; nt < 8; nt++) {           // conflict-free half2 stores
        int col = nt * 8 + c0;
        *(__half2*)&sEh[r0 * 72 + col] = __floats2half2_rn(
            exp2f(acc[nt][0] * LOG2E_O8), exp2f(acc[nt][1] * LOG2E_O8));
        *(__half2*)&sEh[(r0 + 8) * 72 + col] = __floats2half2_rn(
            exp2f(acc[nt][2] * LOG2E_O8), exp2f(acc[nt][3] * LOG2E_O8));
    }
    __syncthreads();
#pragma unroll
    for (int i4 = threadIdx.x; i4 < 512; i4 += 128) {   // 16B copies
        int r = i4 >> 3, c8 = (i4 & 7) * 8;
        ((int4*)po)[i4] = *(int4*)&sEh[r * 72 + c8];
    }
}

// ---------- K2: zinv = 1 / sum_n P (R12 measured-best: 512 blocks, half2) ---
__global__ void __launch_bounds__(256) k_zsum() {
    int c2 = blockIdx.x * 256 + threadIdx.x;      // 131072 half2 columns
    const __half2* p = (const __half2*)g_P + c2;
    float zx = 0.f, zy = 0.f;
#pragma unroll 16
    for (int n = 0; n < NB; n++) {
        float2 v = __half22float2(p[(size_t)n * 131072]);
        zx += v.x; zy += v.y;
    }
    int c = c2 * 2;
    g_zinv[c]     = (zx > 0.f) ? (1.f / zx) : 0.f;
    g_zinv[c + 1] = (zy > 0.f) ? (1.f / zy) : 0.f;
}

// ---------- K3: X[b*256+n][qh*64+d] ----------
// att in natural [l][b] layout; A via ldmatrix.trans; fp16 epilogue staging.
__global__ void __launch_bounds__(128) k_attv() {
    __shared__ __half sbuf[2 * 64 * 72];
    __half* sP  = sbuf;                 // [l][b] scaled att
    __half* sV  = sbuf + 64 * 72;       // [d][l]
    __half* sOh = sbuf;                 // aliased after MMA, [b][d] stride 72
    int n  = blockIdx.x >> 6;
    int qh = blockIdx.x & 63;
#pragma unroll
    for (int i4 = threadIdx.x; i4 < 512; i4 += 128) {   // sV fill, 16B
        int d = i4 >> 3, lc = (i4 & 7) * 8;
        *(int4*)&sV[d * 72 + lc] = *(const int4*)&g_vsumT[n * 4096 + d * 64 + lc];
    }
#pragma unroll
    for (int i4 = threadIdx.x; i4 < 512; i4 += 128) {
        int l = i4 >> 3, b = (i4 & 7) * 8;
        int4 pr = *(const int4*)&g_P[((size_t)(n * 64 + l)) * 4096 + qh * 64 + b];
        __half2* ph = (__half2*)&pr;
        const float* zp = &g_zinv[(l * 64 + qh) * 64 + b];
        float4 z0 = *(const float4*)zp;
        float4 z1 = *(const float4*)(zp + 4);
        __half2 h[4];
        {
            float2 p0 = __half22float2(ph[0]);
            float2 p1 = __half22float2(ph[1]);
            float2 p2 = __half22float2(ph[2]);
            float2 p3 = __half22float2(ph[3]);
            h[0] = __floats2half2_rn(p0.x * z0.x, p0.y * z0.y);
            h[1] = __floats2half2_rn(p1.x * z0.z, p1.y * z0.w);
            h[2] = __floats2half2_rn(p2.x * z1.x, p2.y * z1.y);
            h[3] = __floats2half2_rn(p3.x * z1.z, p3.y * z1.w);
        }
        *(int4*)&sP[l * 72 + b] = *(int4*)h;   // conflict-free 16B store
    }
    __syncthreads();
    float acc[8][4];
#pragma unroll
    for (int i = 0; i < 8; i++) acc[i][0] = acc[i][1] = acc[i][2] = acc[i][3] = 0.f;
    {
        int w = threadIdx.x >> 5, lane = threadIdx.x & 31;
        int lr = lane & 15, lc = lane >> 4;
        int tr = (lane & 7) + ((lane >> 4) << 3);
        int tc = ((lane >> 3) & 1) << 3;
#pragma unroll
        for (int kt = 0; kt < 4; kt++) {
            uint32_t af[4];
            ldm_x4_t(af, &sP[(kt * 16 + tr) * 72 + w * 16 + tc]);
#pragma unroll
            for (int bp = 0; bp < 4; bp++) {
                uint32_t bf[4];
                ldm_x4(bf, &sV[(bp * 16 + lr) * 72 + kt * 16 + lc * 8]);
                mma16816(acc[bp * 2],     af, bf[0], bf[2]);
                mma16816(acc[bp * 2 + 1], af, bf[1], bf[3]);
            }
        }
    }
    __syncthreads();                   // sP/sV dead; reuse as sOh
    int lane = threadIdx.x & 31, w = threadIdx.x >> 5;
    int r0 = w * 16 + (lane >> 2), c0 = (lane & 3) * 2;
#pragma unroll
    for (int nt = 0; nt < 8; nt++) {   // conflict-free half2 stores
        int col = nt * 8 + c0;
        *(__half2*)&sOh[r0 * 72 + col] = __floats2half2_rn(acc[nt][0], acc[nt][1]);
        *(__half2*)&sOh[(r0 + 8) * 72 + col] = __floats2half2_rn(acc[nt][2], acc[nt][3]);
    }
    __syncthreads();
#pragma unroll
    for (int i4 = threadIdx.x; i4 < 512; i4 += 128) {   // 16B X copies
        int b = i4 >> 3, d = (i4 & 7) * 8;
        *(int4*)&g_X[((size_t)(b * 256 + n)) * EMB + qh * 64 + d] = *(int4*)&sOh[b * 72 + d];
    }
}

// ---------- K4: out = X @ W^T / 256 + bias (measured-best config, unchanged) --
#define BM 128
#define BN 128
#define BK 64
#define SST 72
#define A_STG (BM * SST)
#define B_STG (BN * SST)
#define GSMEM (2 * (A_STG + B_STG) * 2)      // 73728 B

__global__ void __launch_bounds__(256, 2) k_gemm(const float* __restrict__ bias,
                                                 float* __restrict__ out) {
    extern __shared__ __half smem[];
    __half* sA = smem;
    __half* sB = smem + 2 * A_STG;

    int tid = threadIdx.x;
    int pn = blockIdx.x, pm = blockIdx.y;    // pn inner => W L2-resident
    const __half* gA = g_X  + (size_t)(pm * BM) * EMB;
    const __half* gB = g_wh + (size_t)(pn * BN) * EMB;

    auto load_stage = [&](int kt, int s) {
#pragma unroll
        for (int i = 0; i < 4; i++) {
            int ch = tid + i * 256;
            int row = ch >> 3, c8 = ch & 7;
            uint32_t d = (uint32_t)__cvta_generic_to_shared(&sA[s * A_STG + row * SST + c8 * 8]);
            cp16(d, gA + (size_t)row * EMB + kt * BK + c8 * 8);
        }
#pragma unroll
        for (int i = 0; i < 4; i++) {
            int ch = tid + i * 256;
            int row = ch >> 3, c8 = ch & 7;
            uint32_t d = (uint32_t)__cvta_generic_to_shared(&sB[s * B_STG + row * SST + c8 * 8]);
            cp16(d, gB + (size_t)row * EMB + kt * BK + c8 * 8);
        }
    };

    int w = tid >> 5, lane = tid & 31;
    int wm = (w & 1) * 64, wn = (w >> 1) * 32;
    int lr = lane & 15, lc = lane >> 4;

    float acc[4][4][4];
#pragma unroll
    for (int m = 0; m < 4; m++)
#pragma unroll
        for (int nn = 0; nn < 4; nn++)
#pragma unroll
            for (int x = 0; x < 4; x++) acc[m][nn][x] = 0.f;

    const int KT = EMB / BK;   // 64
    load_stage(0, 0); CP_COMMIT();

    for (int kt = 0; kt < KT; kt++) {
        CP_WAIT(0);
        __syncthreads();
        if (kt + 1 < KT) { load_stage(kt + 1, (kt + 1) & 1); CP_COMMIT(); }
        const __half* cA = sA + (kt & 1) * A_STG;
        const __half* cB = sB + (kt & 1) * B_STG;
#pragma unroll
        for (int ks = 0; ks < 4; ks++) {
            uint32_t af[4][4];
#pragma unroll
            for (int mt = 0; mt < 4; mt++)
                ldm_x4(af[mt], &cA[(wm + mt * 16 + lr) * SST + ks * 16 + lc * 8]);
#pragma unroll
            for (int ng = 0; ng < 2; ng++) {
                uint32_t bf[4];
                ldm_x4(bf, &cB[(wn + ng * 16 + lr) * SST + ks * 16 + lc * 8]);
#pragma unroll
                for (int mt = 0; mt < 4; mt++) {
                    mma16816(acc[mt][ng * 2],     af[mt], bf[0], bf[2]);
                    mma16816(acc[mt][ng * 2 + 1], af[mt], bf[1], bf[3]);
                }
            }
        }
    }

    int r = lane >> 2, c = (lane & 3) * 2;
#pragma unroll
    for (int mt = 0; mt < 4; mt++) {
        int row0 = pm * BM + wm + mt * 16 + r;
#pragma unroll
        for (int nt = 0; nt < 4; nt++) {
            int col = pn * BN + wn + nt * 8 + c;
            float b0 = bias[col], b1 = bias[col + 1];
            size_t o0 = (size_t)row0 * EMB + col;
            out[o0]     = acc[mt][nt][0] * INV_WSCALE + b0;
            out[o0 + 1] = acc[mt][nt][1] * INV_WSCALE + b1;
            size_t o1 = (size_t)(row0 + 8) * EMB + col;
            out[o1]     = acc[mt][nt][2] * INV_WSCALE + b0;
            out[o1 + 1] = acc[mt][nt][3] * INV_WSCALE + b1;
        }
    }
}

// ---------- launch ----------
extern "C" void kernel_launch(void* const* d_in, const int* in_sizes, int n_in,
                              void* d_out, int out_size) {
    const float* values = (const float*)d_in[0];
    const float* keys   = (const float*)d_in[1];
    const float* query  = (const float*)d_in[2];
    const int*   mask   = (const int*)d_in[3];
    const float* w_out  = (const float*)d_in[4];
    const float* b_out  = (const float*)d_in[5];
    float* out = (float*)d_out;

    cudaFuncSetAttribute(k_gemm, cudaFuncAttributeMaxDynamicSharedMemorySize, GSMEM);

    k_prep<<<3072, 1024>>>(w_out, values);
    k_energy<<<NB * SL, 128>>>(query, keys, mask);
    k_zsum<<<512, 256>>>();
    k_attv<<<NB * NH, 128>>>();
    dim3 g5(EMB / BN, (NB * NH) / BM);   // (32, 128), pn inner
    k_gemm<<<g5, 256, GSMEM>>>(b_out, out);
}

// round 17
// speedup vs baseline: 1.5293x; 1.0155x over previous
#include <cuda_runtime.h>
#include <cuda_fp16.h>
#include <cstdint>
#include <cstddef>

#define NB  256
#define SL  64
#define NH  64
#define HD  64
#define EMB 4096
#define LOG2E_O8 0.1803368801111204f
#define WSCALE    256.0f
#define INV_WSCALE 0.00390625f

// g_P / g_vsumT: masked (n,l) tiles/rows are NEVER written by any kernel;
// device globals are zero-initialized (.bss), so they read deterministically
// as 0, and att[b,l]=0 for masked l makes the results bit-identical.
__device__ __half g_wh[(size_t)EMB * EMB];            // fp16(w*256) [N][K]
__device__ __half g_vsumT[NB * HD * SL];              // [n][d][l]; masked (n,l) stay 0
__device__ __half g_P[(size_t)NB * SL * NH * NH];     // fp16 exp(E/8); masked tiles stay 0
__device__ float  g_zinv[SL * NH * NH];               // [l][a][b]
__device__ __half g_X[(size_t)NB * NH * EMB];         // [16384][4096]

// ---------- helpers ----------
__device__ __forceinline__ void cp16(uint32_t dst, const void* src) {
    asm volatile("cp.async.cg.shared.global [%0], [%1], 16;" :: "r"(dst), "l"(src));
}
#define CP_COMMIT() asm volatile("cp.async.commit_group;" ::: "memory")
#define CP_WAIT(n)  asm volatile("cp.async.wait_group %0;" :: "n"(n) : "memory")

__device__ __forceinline__ void ldm_x4(uint32_t* r, const __half* p) {
    uint32_t a = (uint32_t)__cvta_generic_to_shared(p);
    asm volatile("ldmatrix.sync.aligned.m8n8.x4.shared.b16 {%0,%1,%2,%3}, [%4];"
                 : "=r"(r[0]), "=r"(r[1]), "=r"(r[2]), "=r"(r[3]) : "r"(a));
}
__device__ __forceinline__ void ldm_x4_t(uint32_t* r, const __half* p) {
    uint32_t a = (uint32_t)__cvta_generic_to_shared(p);
    asm volatile("ldmatrix.sync.aligned.m8n8.x4.trans.shared.b16 {%0,%1,%2,%3}, [%4];"
                 : "=r"(r[0]), "=r"(r[1]), "=r"(r[2]), "=r"(r[3]) : "r"(a));
}
__device__ __forceinline__ void mma16816(float* c, const uint32_t* a, uint32_t b0, uint32_t b1) {
    asm volatile(
        "mma.sync.aligned.m16n8k16.row.col.f32.f16.f16.f32 "
        "{%0,%1,%2,%3}, {%4,%5,%6,%7}, {%8,%9}, {%0,%1,%2,%3};"
        : "+f"(c[0]), "+f"(c[1]), "+f"(c[2]), "+f"(c[3])
        : "r"(a[0]), "r"(a[1]), "r"(a[2]), "r"(a[3]), "r"(b0), "r"(b1));
}
__device__ __forceinline__ void gemm64_core(const __half* sA, const __half* sB, float acc[8][4]) {
    int w = threadIdx.x >> 5, lane = threadIdx.x & 31;
    int lr = lane & 15, lc = lane >> 4;
#pragma unroll
    for (int kt = 0; kt < 4; kt++) {
        uint32_t af[4];
        ldm_x4(af, &sA[(w * 16 + lr) * 72 + kt * 16 + lc * 8]);
#pragma unroll
        for (int bp = 0; bp < 4; bp++) {
            uint32_t bf[4];
            ldm_x4(bf, &sB[(bp * 16 + lr) * 72 + kt * 16 + lc * 8]);
            mma16816(acc[bp * 2],     af, bf[0], bf[2]);
            mma16816(acc[bp * 2 + 1], af, bf[1], bf[3]);
        }
    }
}

// ---------- K0: merged weight-convert (16B stores) + masked Vsum ----------
__global__ void __launch_bounds__(1024) k_prep(const float* __restrict__ w,
                                               const float* __restrict__ values,
                                               const int* __restrict__ mask) {
    int b = blockIdx.x;
    if (b < 2048) {                       // convw: 2.1M threads x 2 float4 -> 1 int4
        size_t i2 = (size_t)b * 1024 + threadIdx.x;
        const float4* w4 = (const float4*)w;
        float4 a = w4[i2 * 2];
        float4 c = w4[i2 * 2 + 1];
        __half2 h[4];
        h[0] = __floats2half2_rn(a.x * WSCALE, a.y * WSCALE);
        h[1] = __floats2half2_rn(a.z * WSCALE, a.w * WSCALE);
        h[2] = __floats2half2_rn(c.x * WSCALE, c.y * WSCALE);
        h[3] = __floats2half2_rn(c.z * WSCALE, c.w * WSCALE);
        ((int4*)g_wh)[i2] = *(int4*)h;
    } else {                              // vsum (skip masked (n,l): rows stay 0,
        int t = (b - 2048) * 1024 + threadIdx.x;   //  consumed only by att=0)
        int d = t & 63, l = (t >> 6) & 63, n = t >> 12;
        if (mask[n * 64 + l] == 0) return;         // warp-uniform branch
        const float* p = values + ((size_t)(n * 64 + l)) * EMB + d;
        float s = 0.f;
#pragma unroll
        for (int v = 0; v < 64; v++) s += p[v * 64];
        g_vsumT[(n * 64 + d) * 64 + l] = __float2half_rn(s);
    }
}

// ---------- K1: P[n][l][a][b] = exp(E/8), unmasked tiles only ----------
__global__ void __launch_bounds__(128) k_energy(const float* __restrict__ q,
                                                const float* __restrict__ kk,
                                                const int* __restrict__ mask) {
    __shared__ __half sbuf[2 * 64 * 72];       // sA | sB; sEh aliased after MMA
    __half* sA  = sbuf;
    __half* sB  = sbuf + 64 * 72;
    __half* sEh = sbuf;                        // 64*72 halves
    int nl = blockIdx.x;
    if (mask[nl] == 0) return;                 // tile stays 0 (never written)
    __half* po = g_P + (size_t)nl * 4096;
    const float* qr = q  + (size_t)nl * EMB;
    const float* kr = kk + (size_t)nl * EMB;
#pragma unroll
    for (int i = threadIdx.x; i < 1024; i += 128) {   // float4 loads
        int r = i >> 4, cq = (i & 15) * 4;
        float4 v = ((const float4*)qr)[i];
        __half2* d = (__half2*)&sA[r * 72 + cq];
        d[0] = __floats2half2_rn(v.x, v.y);
        d[1] = __floats2half2_rn(v.z, v.w);
        float4 u = ((const float4*)kr)[i];
        __half2* e = (__half2*)&sB[r * 72 + cq];
        e[0] = __floats2half2_rn(u.x, u.y);
        e[1] = __floats2half2_rn(u.z, u.w);
    }
    __syncthreads();
    float acc[8][4];
#pragma unroll
    for (int i = 0; i < 8; i++) acc[i][0] = acc[i][1] = acc[i][2] = acc[i][3] = 0.f;
    gemm64_core(sA, sB, acc);
    __syncthreads();                           // sA/sB dead; reuse as sEh
    int lane = threadIdx.x & 31, w = threadIdx.x >> 5;
    int r0 = w * 16 + (lane >> 2), c0 = (lane & 3) * 2;
#pragma unroll
    for (int nt = 0; nt < 8; nt++) {           // conflict-free half2 stores
        int col = nt * 8 + c0;
        *(__half2*)&sEh[r0 * 72 + col] = __floats2half2_rn(
            exp2f(acc[nt][0] * LOG2E_O8), exp2f(acc[nt][1] * LOG2E_O8));
        *(__half2*)&sEh[(r0 + 8) * 72 + col] = __floats2half2_rn(
            exp2f(acc[nt][2] * LOG2E_O8), exp2f(acc[nt][3] * LOG2E_O8));
    }
    __syncthreads();
#pragma unroll
    for (int i4 = threadIdx.x; i4 < 512; i4 += 128) {   // 16B copies
        int r = i4 >> 3, c8 = (i4 & 7) * 8;
        ((int4*)po)[i4] = *(int4*)&sEh[r * 72 + c8];
    }
}

// ---------- K2: zinv = 1 / sum_n P (512 blocks, half2 streaming) ----------
__global__ void __launch_bounds__(256) k_zsum() {
    int c2 = blockIdx.x * 256 + threadIdx.x;      // 131072 half2 columns
    const __half2* p = (const __half2*)g_P + c2;
    float zx = 0.f, zy = 0.f;
#pragma unroll 16
    for (int n = 0; n < NB; n++) {
        float2 v = __half22float2(p[(size_t)n * 131072]);
        zx += v.x; zy += v.y;
    }
    int c = c2 * 2;
    g_zinv[c]     = (zx > 0.f) ? (1.f / zx) : 0.f;
    g_zinv[c + 1] = (zy > 0.f) ? (1.f / zy) : 0.f;
}

// ---------- K3: X[b*256+n][qh*64+d] ----------
// att in natural [l][b] layout; A via ldmatrix.trans; fp16 epilogue staging.
__global__ void __launch_bounds__(128) k_attv() {
    __shared__ __half sbuf[2 * 64 * 72];
    __half* sP  = sbuf;                 // [l][b] scaled att
    __half* sV  = sbuf + 64 * 72;       // [d][l]
    __half* sOh = sbuf;                 // aliased after MMA, [b][d] stride 72
    int n  = blockIdx.x >> 6;
    int qh = blockIdx.x & 63;
#pragma unroll
    for (int i4 = threadIdx.x; i4 < 512; i4 += 128) {   // sV fill, 16B
        int d = i4 >> 3, lc = (i4 & 7) * 8;
        *(int4*)&sV[d * 72 + lc] = *(const int4*)&g_vsumT[n * 4096 + d * 64 + lc];
    }
#pragma unroll
    for (int i4 = threadIdx.x; i4 < 512; i4 += 128) {
        int l = i4 >> 3, b = (i4 & 7) * 8;
        int4 pr = *(const int4*)&g_P[((size_t)(n * 64 + l)) * 4096 + qh * 64 + b];
        __half2* ph = (__half2*)&pr;
        const float* zp = &g_zinv[(l * 64 + qh) * 64 + b];
        float4 z0 = *(const float4*)zp;
        float4 z1 = *(const float4*)(zp + 4);
        __half2 h[4];
        {
            float2 p0 = __half22float2(ph[0]);
            float2 p1 = __half22float2(ph[1]);
            float2 p2 = __half22float2(ph[2]);
            float2 p3 = __half22float2(ph[3]);
            h[0] = __floats2half2_rn(p0.x * z0.x, p0.y * z0.y);
            h[1] = __floats2half2_rn(p1.x * z0.z, p1.y * z0.w);
            h[2] = __floats2half2_rn(p2.x * z1.x, p2.y * z1.y);
            h[3] = __floats2half2_rn(p3.x * z1.z, p3.y * z1.w);
        }
        *(int4*)&sP[l * 72 + b] = *(int4*)h;   // conflict-free 16B store
    }
    __syncthreads();
    float acc[8][4];
#pragma unroll
    for (int i = 0; i < 8; i++) acc[i][0] = acc[i][1] = acc[i][2] = acc[i][3] = 0.f;
    {
        int w = threadIdx.x >> 5, lane = threadIdx.x & 31;
        int lr = lane & 15, lc = lane >> 4;
        int tr = (lane & 7) + ((lane >> 4) << 3);
        int tc = ((lane >> 3) & 1) << 3;
#pragma unroll
        for (int kt = 0; kt < 4; kt++) {
            uint32_t af[4];
            ldm_x4_t(af, &sP[(kt * 16 + tr) * 72 + w * 16 + tc]);
#pragma unroll
            for (int bp = 0; bp < 4; bp++) {
                uint32_t bf[4];
                ldm_x4(bf, &sV[(bp * 16 + lr) * 72 + kt * 16 + lc * 8]);
                mma16816(acc[bp * 2],     af, bf[0], bf[2]);
                mma16816(acc[bp * 2 + 1], af, bf[1], bf[3]);
            }
        }
    }
    __syncthreads();                   // sP/sV dead; reuse as sOh
    int lane = threadIdx.x & 31, w = threadIdx.x >> 5;
    int r0 = w * 16 + (lane >> 2), c0 = (lane & 3) * 2;
#pragma unroll
    for (int nt = 0; nt < 8; nt++) {   // conflict-free half2 stores
        int col = nt * 8 + c0;
        *(__half2*)&sOh[r0 * 72 + col] = __floats2half2_rn(acc[nt][0], acc[nt][1]);
        *(__half2*)&sOh[(r0 + 8) * 72 + col] = __floats2half2_rn(acc[nt][2], acc[nt][3]);
    }
    __syncthreads();
#pragma unroll
    for (int i4 = threadIdx.x; i4 < 512; i4 += 128) {   // 16B X copies
        int b = i4 >> 3, d = (i4 & 7) * 8;
        *(int4*)&g_X[((size_t)(b * 256 + n)) * EMB + qh * 64 + d] = *(int4*)&sOh[b * 72 + d];
    }
}

// ---------- K4: out = X @ W^T / 256 + bias (measured-best config, unchanged) --
#define BM 128
#define BN 128
#define BK 64
#define SST 72
#define A_STG (BM * SST)
#define B_STG (BN * SST)
#define GSMEM (2 * (A_STG + B_STG) * 2)      // 73728 B

__global__ void __launch_bounds__(256, 2) k_gemm(const float* __restrict__ bias,
                                                 float* __restrict__ out) {
    extern __shared__ __half smem[];
    __half* sA = smem;
    __half* sB = smem + 2 * A_STG;

    int tid = threadIdx.x;
    int pn = blockIdx.x, pm = blockIdx.y;    // pn inner => W L2-resident
    const __half* gA = g_X  + (size_t)(pm * BM) * EMB;
    const __half* gB = g_wh + (size_t)(pn * BN) * EMB;

    auto load_stage = [&](int kt, int s) {
#pragma unroll
        for (int i = 0; i < 4; i++) {
            int ch = tid + i * 256;
            int row = ch >> 3, c8 = ch & 7;
            uint32_t d = (uint32_t)__cvta_generic_to_shared(&sA[s * A_STG + row * SST + c8 * 8]);
            cp16(d, gA + (size_t)row * EMB + kt * BK + c8 * 8);
        }
#pragma unroll
        for (int i = 0; i < 4; i++) {
            int ch = tid + i * 256;
            int row = ch >> 3, c8 = ch & 7;
            uint32_t d = (uint32_t)__cvta_generic_to_shared(&sB[s * B_STG + row * SST + c8 * 8]);
            cp16(d, gB + (size_t)row * EMB + kt * BK + c8 * 8);
        }
    };

    int w = tid >> 5, lane = tid & 31;
    int wm = (w & 1) * 64, wn = (w >> 1) * 32;
    int lr = lane & 15, lc = lane >> 4;

    float acc[4][4][4];
#pragma unroll
    for (int m = 0; m < 4; m++)
#pragma unroll
        for (int nn = 0; nn < 4; nn++)
#pragma unroll
            for (int x = 0; x < 4; x++) acc[m][nn][x] = 0.f;

    const int KT = EMB / BK;   // 64
    load_stage(0, 0); CP_COMMIT();

    for (int kt = 0; kt < KT; kt++) {
        CP_WAIT(0);
        __syncthreads();
        if (kt + 1 < KT) { load_stage(kt + 1, (kt + 1) & 1); CP_COMMIT(); }
        const __half* cA = sA + (kt & 1) * A_STG;
        const __half* cB = sB + (kt & 1) * B_STG;
#pragma unroll
        for (int ks = 0; ks < 4; ks++) {
            uint32_t af[4][4];
#pragma unroll
            for (int mt = 0; mt < 4; mt++)
                ldm_x4(af[mt], &cA[(wm + mt * 16 + lr) * SST + ks * 16 + lc * 8]);
#pragma unroll
            for (int ng = 0; ng < 2; ng++) {
                uint32_t bf[4];
                ldm_x4(bf, &cB[(wn + ng * 16 + lr) * SST + ks * 16 + lc * 8]);
#pragma unroll
                for (int mt = 0; mt < 4; mt++) {
                    mma16816(acc[mt][ng * 2],     af[mt], bf[0], bf[2]);
                    mma16816(acc[mt][ng * 2 + 1], af[mt], bf[1], bf[3]);
                }
            }
        }
    }

    int r = lane >> 2, c = (lane & 3) * 2;
#pragma unroll
    for (int mt = 0; mt < 4; mt++) {
        int row0 = pm * BM + wm + mt * 16 + r;
#pragma unroll
        for (int nt = 0; nt < 4; nt++) {
            int col = pn * BN + wn + nt * 8 + c;
            float b0 = bias[col], b1 = bias[col + 1];
            size_t o0 = (size_t)row0 * EMB + col;
            out[o0]     = acc[mt][nt][0] * INV_WSCALE + b0;
            out[o0 + 1] = acc[mt][nt][1] * INV_WSCALE + b1;
            size_t o1 = (size_t)(row0 + 8) * EMB + col;
            out[o1]     = acc[mt][nt][2] * INV_WSCALE + b0;
            out[o1 + 1] = acc[mt][nt][3] * INV_WSCALE + b1;
        }
    }
}

// ---------- launch ----------
extern "C" void kernel_launch(void* const* d_in, const int* in_sizes, int n_in,
                              void* d_out, int out_size) {
    const float* values = (const float*)d_in[0];
    const float* keys   = (const float*)d_in[1];
    const float* query  = (const float*)d_in[2];
    const int*   mask   = (const int*)d_in[3];
    const float* w_out  = (const float*)d_in[4];
    const float* b_out  = (const float*)d_in[5];
    float* out = (float*)d_out;

    cudaFuncSetAttribute(k_gemm, cudaFuncAttributeMaxDynamicSharedMemorySize, GSMEM);

    k_prep<<<3072, 1024>>>(w_out, values, mask);
    k_energy<<<NB * SL, 128>>>(query, keys, mask);
    k_zsum<<<512, 256>>>();
    k_attv<<<NB * NH, 128>>>();
    dim3 g5(EMB / BN, (NB * NH) / BM);   // (32, 128), pn inner
    k_gemm<<<g5, 256, GSMEM>>>(b_out, out);
}